// round 12
// baseline (speedup 1.0000x reference)
#include <cuda_runtime.h>
#include <cstdint>

#define TT 1024
#define NTHR 128
#define NBLK 512
#define DEPTH 5

struct Q { float w, x, y, z; };
struct V3 { float x, y, z; };

__device__ __forceinline__ Q qmul(const Q a, const Q b) {
    return Q{ a.w*b.w - a.x*b.x - a.y*b.y - a.z*b.z,
              a.w*b.x + a.x*b.w + a.y*b.z - a.z*b.y,
              a.w*b.y - a.x*b.z + a.y*b.w + a.z*b.x,
              a.w*b.z + a.x*b.y - a.y*b.x + a.z*b.w };
}
__device__ __forceinline__ V3 qrot(const Q q, const V3 v) {
    float tx = 2.0f*(q.y*v.z - q.z*v.y);
    float ty = 2.0f*(q.z*v.x - q.x*v.z);
    float tz = 2.0f*(q.x*v.y - q.y*v.x);
    return V3{ v.x + q.w*tx + (q.y*tz - q.z*ty),
               v.y + q.w*ty + (q.z*tx - q.x*tz),
               v.z + q.w*tz + (q.x*ty - q.y*tx) };
}
// ||R(a)-R(b)||_F^2 = 8*(1 - dot(a,b)^2) for unit quats
__device__ __forceinline__ float qdot(const Q a, const Q b) {
    return fmaf(a.w, b.w, fmaf(a.x, b.x, fmaf(a.y, b.y, a.z*b.z)));
}
__device__ __forceinline__ float n2(const V3 a) {
    return fmaf(a.x, a.x, fmaf(a.y, a.y, a.z*a.z));
}

__device__ __forceinline__ uint32_t smem_u32(const void* p) {
    return (uint32_t)__cvta_generic_to_shared(p);
}
__device__ __forceinline__ void cp16(uint32_t dst, const float* src) {
    asm volatile("cp.async.cg.shared.global [%0], [%1], 16;\n" :: "r"(dst), "l"(src));
}
__device__ __forceinline__ void commitg() {
    asm volatile("cp.async.commit_group;\n" ::: "memory");
}
template<int N>
__device__ __forceinline__ void waitg() {
    asm volatile("cp.async.wait_group %0;\n" :: "n"(N) : "memory");
}

// denorm + normalize a quat from a stage buffer (channels cbase..cbase+3 at lane tid)
__device__ __forceinline__ Q mkq_s(const float* R, int cbase, const float* mn,
                                   const float* sd, int mc, int tid) {
    float w = fmaf(R[(cbase+0)*128+tid], sd[mc+0], mn[mc+0]);
    float x = fmaf(R[(cbase+1)*128+tid], sd[mc+1], mn[mc+1]);
    float y = fmaf(R[(cbase+2)*128+tid], sd[mc+2], mn[mc+2]);
    float z = fmaf(R[(cbase+3)*128+tid], sd[mc+3], mn[mc+3]);
    float inv = rsqrtf(fmaf(w, w, fmaf(x, x, fmaf(y, y, z*z))));
    return Q{w*inv, x*inv, y*inv, z*inv};
}

__device__ float g_part[NBLK];
__device__ unsigned int g_ctr = 0;

__global__ void __launch_bounds__(NTHR) fk_loss_kernel(
    const float* __restrict__ ik,   // (64, 168, 1024)
    const float* __restrict__ dec,  // (64, 176, 1024)
    const float* __restrict__ tgt,  // (64, 176, 1024)
    const float* __restrict__ mean, // (176,)
    const float* __restrict__ stdv, // (176,)
    const float* __restrict__ offs, // (22, 3)
    float* __restrict__ out)
{
    // ring FIRST and 16B-aligned: cp.async 16B chunks need 16B-aligned smem dst
    __shared__ __align__(16) float ring[DEPTH][12*128];
    __shared__ float smn[176], ssd[176], soff[66];

    int tid = threadIdx.x;
    for (int i = tid; i < 176; i += NTHR) { smn[i] = mean[i]; ssd[i] = stdv[i]; }
    for (int i = tid; i < 66; i += NTHR) soff[i] = offs[i];

    int b  = blockIdx.x >> 3;
    int t0 = (blockIdx.x & 7) << 7;     // 128-t tile
    const float* ikp = ik  + (size_t)b * 168 * TT + t0;
    const float* dcp = dec + (size_t)b * 176 * TT + t0;
    const float* tgp = tgt + (size_t)b * 176 * TT + t0;

    // issue one joint-stage: 12 channels x 128 floats = 6KB as 16B cp.async chunks
    auto issue = [&](int j, float* buf) {
        uint32_t base = smem_u32(buf);
#pragma unroll
        for (int m = 0; m < 3; m++) {
            int k  = tid + m * 128;       // chunk id 0..383
            int c  = k >> 5;              // channel slot 0..11 (uniform per warp)
            int i4 = (k & 31) << 2;       // float offset in t-row
            const float* g;
            if (c < 4)      g = ikp + (size_t)((j-1)*8 + c)     * TT + i4;
            else if (c < 8) g = dcp + (size_t)(j*8 + (c-4))     * TT + i4;
            else            g = tgp + (size_t)(j*8 + (c-8))     * TT + i4;
            cp16(base + (uint32_t)k * 16, g);
        }
        commitg();
    };

    // prologue: fill 4 stages (joints 1..4)
    issue(1, ring[0]); issue(2, ring[1]); issue(3, ring[2]); issue(4, ring[3]);

    __syncthreads();   // constants (smn/ssd/soff) ready

    // target root quat via plain loads (overlaps pipeline fill); conj folded
    Q qc0;
    {
        float w0 = fmaf(tgp[0*TT + tid], ssd[0], smn[0]);
        float x0 = fmaf(tgp[1*TT + tid], ssd[1], smn[1]);
        float y0 = fmaf(tgp[2*TT + tid], ssd[2], smn[2]);
        float z0 = fmaf(tgp[3*TT + tid], ssd[3], smn[3]);
        float inv = rsqrtf(fmaf(w0, w0, fmaf(x0, x0, fmaf(y0, y0, z0*z0))));
        qc0 = Q{w0*inv, -x0*inv, -y0*inv, -z0*inv};
    }

    // telescoped globals: rots[j] = conj(qr0)*qr_j (ik/dec roots identity)
    Q  gI[22], gD[22], gT[22];
    V3 dDI[22], dIT[22];   // pD - pI, pI - pT
    float aep = 0.0f, aer = 0.0f, anp = 0.0f, anr = 0.0f;

#define STEP_NS(R, j, p) do {                                                  \
    Q qi = mkq_s(R, 0, smn, ssd, (j)*8, tid);                                  \
    Q qd = mkq_s(R, 4, smn, ssd, (j)*8, tid);                                  \
    Q qt = mkq_s(R, 8, smn, ssd, (j)*8, tid);                                  \
    gI[j] = qi; gD[j] = qd; gT[j] = qmul(qc0, qt);                             \
    if ((p) == 0) {                                                            \
        dDI[j] = V3{0.f,0.f,0.f}; dIT[j] = V3{0.f,0.f,0.f};                    \
    } else {                                                                   \
        V3 off = V3{soff[3*(j)], soff[3*(j)+1], soff[3*(j)+2]};                \
        V3 rI = qrot(gI[p], off);                                              \
        V3 rD = qrot(gD[p], off);                                              \
        V3 rT = qrot(gT[p], off);                                              \
        dDI[j] = V3{dDI[p].x + rD.x - rI.x, dDI[p].y + rD.y - rI.y,            \
                    dDI[p].z + rD.z - rI.z};                                   \
        dIT[j] = V3{dIT[p].x + rI.x - rT.x, dIT[p].y + rI.y - rT.y,            \
                    dIT[p].z + rI.z - rT.z};                                   \
        anp += n2(dDI[j]);                                                     \
    }                                                                          \
    { float d = qdot(qd, qi); anr += fmaf(-d, d, 1.0f); }                      \
} while (0)

#define STEP_EE(R, j, p) do {                                                  \
    Q qi = mkq_s(R, 0, smn, ssd, (j)*8, tid);                                  \
    Q qt = mkq_s(R, 8, smn, ssd, (j)*8, tid);                                  \
    Q gt = qmul(qc0, qt);                                                      \
    V3 off = V3{soff[3*(j)], soff[3*(j)+1], soff[3*(j)+2]};                    \
    V3 rI = qrot(gI[p], off);                                                  \
    V3 rT = qrot(gT[p], off);                                                  \
    V3 d = V3{dIT[p].x + rI.x - rT.x, dIT[p].y + rI.y - rT.y,                  \
              dIT[p].z + rI.z - rT.z};                                         \
    aep += n2(d);                                                              \
    { float dd = qdot(qi, gt); aer += fmaf(-dd, dd, 1.0f); }                   \
} while (0)

    // stage s: wait for stage s data, barrier, prefetch next joint, compute.
#define STG(s, WAITN, ISSUE, COMPUTE) do {                                     \
    waitg<WAITN>(); __syncthreads();                                           \
    ISSUE;                                                                     \
    COMPUTE;                                                                   \
} while (0)

    STG(0,  3, issue(5,  ring[4]), STEP_NS(ring[0], 1, 0));
    STG(1,  3, issue(6,  ring[0]), STEP_NS(ring[1], 2, 1));
    STG(2,  3, issue(7,  ring[1]), STEP_NS(ring[2], 3, 2));
    STG(3,  3, issue(8,  ring[2]), STEP_EE(ring[3], 4, 3));
    STG(4,  3, issue(9,  ring[3]), STEP_NS(ring[4], 5, 0));
    STG(5,  3, issue(10, ring[4]), STEP_NS(ring[0], 6, 5));
    STG(6,  3, issue(11, ring[0]), STEP_NS(ring[1], 7, 6));
    STG(7,  3, issue(12, ring[1]), STEP_EE(ring[2], 8, 7));
    STG(8,  3, issue(13, ring[2]), STEP_NS(ring[3], 9, 0));
    STG(9,  3, issue(14, ring[3]), STEP_NS(ring[4], 10, 9));
    STG(10, 3, issue(15, ring[4]), STEP_NS(ring[0], 11, 10));
    STG(11, 3, issue(16, ring[0]), STEP_NS(ring[1], 12, 11));
    STG(12, 3, issue(17, ring[1]), STEP_EE(ring[2], 13, 12));
    STG(13, 3, issue(18, ring[2]), STEP_NS(ring[3], 14, 11));
    STG(14, 3, issue(19, ring[3]), STEP_NS(ring[4], 15, 14));
    STG(15, 3, issue(20, ring[4]), STEP_NS(ring[0], 16, 15));
    STG(16, 3, issue(21, ring[0]), STEP_EE(ring[1], 17, 16));
    STG(17, 3, (void)0,            STEP_NS(ring[2], 18, 11));
    STG(18, 2, (void)0,            STEP_NS(ring[3], 19, 18));
    STG(19, 1, (void)0,            STEP_NS(ring[4], 20, 19));
    STG(20, 0, (void)0,            STEP_EE(ring[0], 21, 20));

#undef STG
#undef STEP_NS
#undef STEP_EE

    const float NBT = 65536.0f;
    float s = aep * (1.0f / (NBT * 15.0f))
            + aer * (8.0f / (NBT * 45.0f))
            + anp * (0.1f / (NBT * 48.0f))
            + anr * (0.8f / (NBT * 144.0f));

    // block reduction -> deterministic per-block partial
#pragma unroll
    for (int o = 16; o; o >>= 1) s += __shfl_down_sync(0xffffffffu, s, o);
    __shared__ float ws[NTHR / 32];
    __shared__ bool is_last;
    if ((tid & 31) == 0) ws[tid >> 5] = s;
    __syncthreads();
    if (tid == 0) {
        float v = 0.0f;
#pragma unroll
        for (int i = 0; i < NTHR / 32; i++) v += ws[i];
        g_part[blockIdx.x] = v;
        __threadfence();
        unsigned int old = atomicAdd(&g_ctr, 1u);
        is_last = (old == NBLK - 1);
    }
    __syncthreads();

    // last-arriving block: deterministic final reduction of 512 partials
    if (is_last && tid < 32) {
        volatile float* vp = g_part;
        float v = 0.0f;
#pragma unroll
        for (int i = 0; i < NBLK / 32; i++) v += vp[tid + i * 32];
#pragma unroll
        for (int o = 16; o; o >>= 1) v += __shfl_down_sync(0xffffffffu, v, o);
        if (tid == 0) {
            out[0] = v;
            g_ctr = 0;   // reset for next graph replay
        }
    }
}

extern "C" void kernel_launch(void* const* d_in, const int* in_sizes, int n_in,
                              void* d_out, int out_size) {
    // metadata order: input(unused), input_ik, input_decoder, target, mean_dqs, std_dqs, offsets
    const float* ik   = (const float*)d_in[1];
    const float* dec  = (const float*)d_in[2];
    const float* tgt  = (const float*)d_in[3];
    const float* mean = (const float*)d_in[4];
    const float* stdv = (const float*)d_in[5];
    const float* offs = (const float*)d_in[6];
    float* out = (float*)d_out;

    fk_loss_kernel<<<NBLK, NTHR>>>(ik, dec, tgt, mean, stdv, offs, out);
}